// round 5
// baseline (speedup 1.0000x reference)
#include <cuda_runtime.h>

// scratch (device globals, no allocation)
__device__ float g_h[33554432];   // [B,256,256,64] activations (128MB)
__device__ float g_G[4194304];    // [B,256m,16ky,64c,2]
__device__ float g_X[524288];     // [B,32kxi,16ky,64c,2]
__device__ float g_O[524288];     // [B,32kxi,16ky,64o,2]
__device__ float g_Y[4194304];    // [B,256m,16ky,64o,2]
__device__ float g_W[16777216];   // [L,32kxi,16ky,64i,64o,2]
__device__ float g_ct[256];
__device__ float g_st[256];

// ---- packed f32x2 helpers (sm_103a) ----
__device__ __forceinline__ unsigned long long f2pk(float lo, float hi) {
    unsigned long long r;
    asm("mov.b64 %0, {%1, %2};" : "=l"(r) : "f"(lo), "f"(hi));
    return r;
}
__device__ __forceinline__ unsigned long long fdup(float v) { return f2pk(v, v); }
__device__ __forceinline__ void ffma2(unsigned long long& d, unsigned long long a,
                                      unsigned long long b) {
    asm("fma.rn.f32x2 %0, %1, %2, %0;" : "+l"(d) : "l"(a), "l"(b));
}
__device__ __forceinline__ void f2un(float& lo, float& hi, unsigned long long v) {
    asm("mov.b64 {%0, %1}, %2;" : "=f"(lo), "=f"(hi) : "l"(v));
}

__global__ void k_tables() {
    int t = threadIdx.x;
    g_ct[t] = cospif(t / 128.0f);
    g_st[t] = sinpif(t / 128.0f);
}

// fw[l][i][o][kx][ky][2] -> g_W[l][kxi][ky][i][o][2]
__global__ void k_wpack(const float* __restrict__ fw1, const float* __restrict__ fw2) {
    int idx = blockIdx.x * 256 + threadIdx.x;
    int o = idx & 63, i = (idx >> 6) & 63, ky = (idx >> 12) & 15;
    int kxi = (idx >> 16) & 31, l = idx >> 21;
    const float* src = (kxi < 16)
        ? fw1 + (size_t)((((l * 64 + i) * 64 + o) * 16 + kxi) * 16 + ky) * 2
        : fw2 + (size_t)((((l * 64 + i) * 64 + o) * 16 + (kxi - 16)) * 16 + ky) * 2;
    ((float2*)g_W)[idx] = *(const float2*)src;
}

// h = feat(5) @ in_w + in_b
__global__ __launch_bounds__(256) void k_inproj(const float* __restrict__ x,
                                                const float* __restrict__ in_w,
                                                const float* __restrict__ in_b) {
    __shared__ float w[320], bsh[64];
    int tid = threadIdx.x;
    w[tid] = in_w[tid & 255];
    if (tid < 64) { w[256 + tid] = in_w[256 + tid]; bsh[tid] = in_b[tid]; }
    __syncthreads();
    int pt = blockIdx.x * 4 + (tid >> 6);
    int c = tid & 63;
    int m = (pt >> 8) & 255, n = pt & 255;
    const float* xp = x + (size_t)pt * 3;
    float x0 = xp[0], x1 = xp[1], x2 = xp[2];
    float pm = (2 * m + 1) * (1.0f / 256.0f) - 1.0f;
    float pn = (2 * n + 1) * (1.0f / 256.0f) - 1.0f;
    g_h[(size_t)pt * 64 + c] = bsh[c] + x0 * w[c] + x1 * w[64 + c] + x2 * w[128 + c]
                             + pm * w[192 + c] + pn * w[256 + c];
}

// fwd real DFT over n: G[ky][c] = sum_n h[n][c] e^{-i 2pi ky n/256}, ky<16
__global__ __launch_bounds__(256) void k_fftn() {
    extern __shared__ float sm[];
    float* hs  = sm;           // 16384
    float* cts = sm + 16384;   // 256
    float* sts = sm + 16640;   // 256
    int tid = threadIdx.x, bm = blockIdx.x;
    cts[tid] = g_ct[tid]; sts[tid] = g_st[tid];
    const float4* src = (const float4*)(g_h + (size_t)bm * 16384);
    float4* d4 = (float4*)hs;
#pragma unroll
    for (int it = 0; it < 16; it++) d4[tid + 256 * it] = src[tid + 256 * it];
    __syncthreads();
    int ky = tid >> 4, c = (tid & 15) * 4;
    float r0 = 0, r1 = 0, r2 = 0, r3 = 0, i0 = 0, i1 = 0, i2 = 0, i3 = 0;
#pragma unroll 4
    for (int n = 0; n < 256; n++) {
        int t = (ky * n) & 255;
        float cv = cts[t], sv = sts[t];
        float4 hv = *(const float4*)(hs + n * 64 + c);
        r0 += hv.x * cv; i0 -= hv.x * sv;
        r1 += hv.y * cv; i1 -= hv.y * sv;
        r2 += hv.z * cv; i2 -= hv.z * sv;
        r3 += hv.w * cv; i3 -= hv.w * sv;
    }
    float4* gp = (float4*)(g_G + (size_t)bm * 2048 + ky * 128 + c * 2);
    gp[0] = make_float4(r0, i0, r1, i1);
    gp[1] = make_float4(r2, i2, r3, i3);
}

// fwd complex DFT over m: X[kxi][c] = sum_m G[m][c] e^{-i 2pi kx m/256}
__global__ __launch_bounds__(512) void k_fftm() {
    __shared__ float2 Gc[4096];     // 64 m x 64 c
    __shared__ float cts[256], sts[256];
    int tid = threadIdx.x;
    int b = blockIdx.x >> 4, ky = blockIdx.x & 15;
    if (tid < 256) { cts[tid] = g_ct[tid]; sts[tid] = g_st[tid]; }
    int kxi = tid >> 4, c = (tid & 15) * 4;
    int kx = kxi < 16 ? kxi : kxi + 224;
    float xr0 = 0, xr1 = 0, xr2 = 0, xr3 = 0, xi0 = 0, xi1 = 0, xi2 = 0, xi3 = 0;
    const float2* src = (const float2*)g_G;
    for (int m0 = 0; m0 < 256; m0 += 64) {
        __syncthreads();
#pragma unroll
        for (int it = 0; it < 8; it++) {
            int e = tid + 512 * it;
            Gc[e] = src[((b * 256 + m0 + (e >> 6)) * 16 + ky) * 64 + (e & 63)];
        }
        __syncthreads();
#pragma unroll 4
        for (int ml = 0; ml < 64; ml++) {
            int t = (kx * (m0 + ml)) & 255;
            float cv = cts[t], sv = sts[t];
            const float4* gg = (const float4*)(Gc + ml * 64 + c);
            float4 a = gg[0], d = gg[1];
            xr0 += a.x * cv + a.y * sv;  xi0 += a.y * cv - a.x * sv;
            xr1 += a.z * cv + a.w * sv;  xi1 += a.w * cv - a.z * sv;
            xr2 += d.x * cv + d.y * sv;  xi2 += d.y * cv - d.x * sv;
            xr3 += d.z * cv + d.w * sv;  xi3 += d.w * cv - d.z * sv;
        }
    }
    float4* dst = (float4*)(g_X + ((size_t)((b * 32 + kxi) * 16 + ky) * 64 + c) * 2);
    dst[0] = make_float4(xr0, xi0, xr1, xi1);
    dst[1] = make_float4(xr2, xi2, xr3, xi3);
}

// per-mode complex mix: O[b][o] = sum_i X[b][i] * W[i][o]
__global__ __launch_bounds__(512) void k_mode(int l) {
    __shared__ float2 Xs[512];
    int tid = threadIdx.x;
    int kxi = blockIdx.x >> 4, ky = blockIdx.x & 15;
    Xs[tid] = ((const float2*)g_X)[(((tid >> 6) * 32 + kxi) * 16 + ky) * 64 + (tid & 63)];
    __syncthreads();
    int b = tid >> 6, o = tid & 63;
    const float2* wp = ((const float2*)g_W) + (size_t)((l * 32 + kxi) * 16 + ky) * 4096;
    float orr = 0.f, oii = 0.f;
#pragma unroll 8
    for (int i = 0; i < 64; i++) {
        float2 xv = Xs[b * 64 + i];
        float2 wv = wp[i * 64 + o];
        orr += xv.x * wv.x - xv.y * wv.y;
        oii += xv.x * wv.y + xv.y * wv.x;
    }
    ((float2*)g_O)[((b * 32 + kxi) * 16 + ky) * 64 + o] = make_float2(orr, oii);
}

// inverse complex DFT over m: Y[m][o] = sum_kxi O[kxi][o] e^{+i 2pi kx m/256}
__global__ __launch_bounds__(512) void k_ifftm() {
    __shared__ float2 Os[2048];   // 32 kxi x 64 o
    __shared__ float cts[256], sts[256];
    int tid = threadIdx.x;
    int b = blockIdx.x >> 4, ky = blockIdx.x & 15;
    if (tid < 256) { cts[tid] = g_ct[tid]; sts[tid] = g_st[tid]; }
#pragma unroll
    for (int it = 0; it < 4; it++) {
        int e = tid + 512 * it;
        Os[e] = ((const float2*)g_O)[((b * 32 + (e >> 6)) * 16 + ky) * 64 + (e & 63)];
    }
    __syncthreads();
    int o = (tid & 15) * 4, mg = tid >> 4;
    for (int p = 0; p < 2; p++) {
        float yr[4][4], yi[4][4];
#pragma unroll
        for (int i = 0; i < 4; i++)
#pragma unroll
            for (int q = 0; q < 4; q++) { yr[i][q] = 0.f; yi[i][q] = 0.f; }
#pragma unroll 2
        for (int kxi = 0; kxi < 32; kxi++) {
            int kx = kxi < 16 ? kxi : kxi + 224;
            const float4* os4 = (const float4*)(Os + kxi * 64 + o);
            float4 a = os4[0], d = os4[1];
#pragma unroll
            for (int i = 0; i < 4; i++) {
                int m = mg + 32 * i + 128 * p;
                int t = (kx * m) & 255;
                float cv = cts[t], sv = sts[t];
                yr[i][0] += a.x * cv - a.y * sv;  yi[i][0] += a.x * sv + a.y * cv;
                yr[i][1] += a.z * cv - a.w * sv;  yi[i][1] += a.z * sv + a.w * cv;
                yr[i][2] += d.x * cv - d.y * sv;  yi[i][2] += d.x * sv + d.y * cv;
                yr[i][3] += d.z * cv - d.w * sv;  yi[i][3] += d.z * sv + d.w * cv;
            }
        }
#pragma unroll
        for (int i = 0; i < 4; i++) {
            int m = mg + 32 * i + 128 * p;
            float4* dst = (float4*)(g_Y + ((size_t)((b * 256 + m) * 16 + ky) * 64 + o) * 2);
            dst[0] = make_float4(yr[i][0], yi[i][0], yr[i][1], yi[i][1]);
            dst[1] = make_float4(yr[i][2], yi[i][2], yr[i][3], yi[i][3]);
        }
    }
}

// inverse real DFT over n + residual dense + relu, fused. One block per (b,m).
__global__ __launch_bounds__(256) void k_iffn(const float* __restrict__ lw,
                                              const float* __restrict__ lb) {
    extern __shared__ float sm[];
    float* ys  = sm;            // 256*65 = 16640 (padded)
    float* lws = sm + 16640;    // 4096
    float* Sre = sm + 20736;    // 1024
    float* Sim = sm + 21760;    // 1024
    float* cts = sm + 22784;    // 256
    float* sts = sm + 23040;    // 256
    float* lbs = sm + 23296;    // 64   -> total 23360 floats = 93440 bytes
    int tid = threadIdx.x, bm = blockIdx.x;
    cts[tid] = g_ct[tid]; sts[tid] = g_st[tid];
    if (tid < 64) lbs[tid] = lb[tid];
#pragma unroll
    for (int it = 0; it < 16; it++) lws[tid + 256 * it] = lw[tid + 256 * it];
    const float2* Yp = (const float2*)g_Y + (size_t)bm * 1024;
#pragma unroll
    for (int it = 0; it < 4; it++) {
        int e = tid + 256 * it;
        int ky = e >> 6, o = e & 63;
        float2 v = Yp[e];
        float sc = (ky == 0 ? 1.f : 2.f) * (1.f / 65536.f);
        Sre[ky * 64 + o] = v.x * sc;
        Sim[ky * 64 + o] = v.y * sc;
    }
    __syncthreads();
    // phase 1: inverse real DFT over n, spectrum register-cached per thread
    {
        int o2 = (tid & 31) * 2, ng = tid >> 5;
        float sr0[16], sr1[16], si0[16], si1[16];
#pragma unroll
        for (int ky = 0; ky < 16; ky++) {
            float2 re = *(const float2*)(Sre + ky * 64 + o2);
            float2 im = *(const float2*)(Sim + ky * 64 + o2);
            sr0[ky] = re.x; sr1[ky] = re.y; si0[ky] = im.x; si1[ky] = im.y;
        }
        for (int j = 0; j < 32; j++) {
            int n = ng * 32 + j;
            float y0 = 0.f, y1 = 0.f;
#pragma unroll
            for (int ky = 0; ky < 16; ky++) {
                int t = (ky * n) & 255;
                float cv = cts[t], sv = sts[t];
                y0 += sr0[ky] * cv - si0[ky] * sv;
                y1 += sr1[ky] * cv - si1[ky] * sv;
            }
            ys[n * 65 + o2] = y0;
            ys[n * 65 + o2 + 1] = y1;
        }
    }
    __syncthreads();
    // phase 2: residual dense + relu; thread = point n, packed f32x2 FMA
    {
        int n = tid;
        float yr[64];
#pragma unroll
        for (int c = 0; c < 64; c++) yr[c] = ys[n * 65 + c];
#pragma unroll
        for (int g = 0; g < 4; g++) {
            int o0 = g * 16;
            unsigned long long acc[8];
#pragma unroll
            for (int q = 0; q < 8; q++) acc[q] = f2pk(lbs[o0 + 2 * q], lbs[o0 + 2 * q + 1]);
#pragma unroll 8
            for (int c = 0; c < 64; c++) {
                unsigned long long hd = fdup(yr[c]);
                const ulonglong2* wp = (const ulonglong2*)(lws + c * 64 + o0);
#pragma unroll
                for (int q = 0; q < 4; q++) {
                    ulonglong2 w = wp[q];
                    ffma2(acc[2 * q], hd, w.x);
                    ffma2(acc[2 * q + 1], hd, w.y);
                }
            }
#pragma unroll
            for (int q = 0; q < 8; q++) {
                float a0, a1;
                f2un(a0, a1, acc[q]);
                float h0 = yr[o0 + 2 * q] + a0;
                float h1 = yr[o0 + 2 * q + 1] + a1;
                ys[n * 65 + o0 + 2 * q]     = h0 > 0.f ? h0 : 0.f;
                ys[n * 65 + o0 + 2 * q + 1] = h1 > 0.f ? h1 : 0.f;
            }
        }
    }
    __syncthreads();
    float* hp = g_h + (size_t)bm * 16384;
#pragma unroll
    for (int it = 0; it < 64; it++) {
        int e = tid + 256 * it;
        hp[e] = ys[(e >> 6) * 65 + (e & 63)];
    }
}

// out = relu(h @ W1 + b1) @ W2 + b2. One block per (b,m), thread = point n.
__global__ __launch_bounds__(256) void k_head(const float* __restrict__ w1,
                                              const float* __restrict__ b1,
                                              const float* __restrict__ w2,
                                              const float* __restrict__ b2,
                                              float* __restrict__ out) {
    extern __shared__ float sm[];
    float* hs  = sm;            // 256*65 = 16640 (padded)
    float* w1s = sm + 16640;    // 64*128 = 8192
    float* w2s = sm + 24832;    // 128
    float* b1s = sm + 24960;    // 128  -> total 25088 floats = 100352 bytes
    int tid = threadIdx.x, bm = blockIdx.x;
    const float* hrow = g_h + (size_t)bm * 16384;
#pragma unroll
    for (int it = 0; it < 64; it++) {
        int e = tid + 256 * it;
        hs[(e >> 6) * 65 + (e & 63)] = hrow[e];
    }
#pragma unroll
    for (int it = 0; it < 32; it++) w1s[tid + 256 * it] = w1[tid + 256 * it];
    if (tid < 128) { w2s[tid] = w2[tid]; b1s[tid] = b1[tid]; }
    __syncthreads();
    float hr[64];
#pragma unroll
    for (int c = 0; c < 64; c++) hr[c] = hs[tid * 65 + c];
    float accf = b2[0];
#pragma unroll
    for (int g = 0; g < 4; g++) {
        int j0 = g * 32;
        unsigned long long acc[16];
#pragma unroll
        for (int q = 0; q < 16; q++) acc[q] = f2pk(b1s[j0 + 2 * q], b1s[j0 + 2 * q + 1]);
#pragma unroll 4
        for (int c = 0; c < 64; c++) {
            unsigned long long hd = fdup(hr[c]);
            const ulonglong2* wp = (const ulonglong2*)(w1s + c * 128 + j0);
#pragma unroll
            for (int q = 0; q < 8; q++) {
                ulonglong2 w = wp[q];
                ffma2(acc[2 * q], hd, w.x);
                ffma2(acc[2 * q + 1], hd, w.y);
            }
        }
#pragma unroll
        for (int q = 0; q < 16; q++) {
            float a0, a1;
            f2un(a0, a1, acc[q]);
            accf += (a0 > 0.f ? a0 : 0.f) * w2s[j0 + 2 * q]
                  + (a1 > 0.f ? a1 : 0.f) * w2s[j0 + 2 * q + 1];
        }
    }
    out[(size_t)bm * 256 + tid] = accf;
}

extern "C" void kernel_launch(void* const* d_in, const int* in_sizes, int n_in,
                              void* d_out, int out_size) {
    const float* x     = (const float*)d_in[0];
    const float* in_w  = (const float*)d_in[1];
    const float* in_b  = (const float*)d_in[2];
    const float* fw1   = (const float*)d_in[3];
    const float* fw2   = (const float*)d_in[4];
    const float* lin_w = (const float*)d_in[5];
    const float* lin_b = (const float*)d_in[6];
    const float* o1w   = (const float*)d_in[7];
    const float* o1b   = (const float*)d_in[8];
    const float* o2w   = (const float*)d_in[9];
    const float* o2b   = (const float*)d_in[10];
    float* out = (float*)d_out;

    cudaFuncSetAttribute(k_fftn, cudaFuncAttributeMaxDynamicSharedMemorySize, 67584);
    cudaFuncSetAttribute(k_iffn, cudaFuncAttributeMaxDynamicSharedMemorySize, 93440);
    cudaFuncSetAttribute(k_head, cudaFuncAttributeMaxDynamicSharedMemorySize, 100352);

    k_tables<<<1, 256>>>();
    k_wpack<<<32768, 256>>>(fw1, fw2);
    k_inproj<<<131072, 256>>>(x, in_w, in_b);
    for (int l = 0; l < 4; l++) {
        k_fftn<<<2048, 256, 67584>>>();
        k_fftm<<<128, 512>>>();
        k_mode<<<512, 512>>>(l);
        k_ifftm<<<128, 512>>>();
        k_iffn<<<2048, 256, 93440>>>(lin_w + l * 4096, lin_b + l * 64);
    }
    k_head<<<2048, 256, 100352>>>(o1w, o1b, o2w, o2b, out);
}

// round 14
// speedup vs baseline: 1.2356x; 1.2356x over previous
#include <cuda_runtime.h>

// scratch (device globals, no allocation)
__device__ float g_G[4194304];    // [B,256m,16ky,64c,2]
__device__ float g_X[524288];     // [B,32kxi,16ky,64c,2]
__device__ float g_O[524288];     // [B,32kxi,16ky,64o,2]
__device__ float g_Y[4194304];    // [B,256m,16ky,64o,2]
__device__ float g_W[16777216];   // [L,32kxi,16ky,64i,64o,2]
__device__ float g_ct[256];
__device__ float g_st[256];

typedef unsigned long long ull;

// ---- packed f32x2 helpers (sm_103a) ----
__device__ __forceinline__ ull f2pk(float lo, float hi) {
    ull r;
    asm("mov.b64 %0, {%1, %2};" : "=l"(r) : "f"(lo), "f"(hi));
    return r;
}
__device__ __forceinline__ ull fdup(float v) { return f2pk(v, v); }
__device__ __forceinline__ void ffma2(ull& d, ull a, ull b) {
    asm("fma.rn.f32x2 %0, %1, %2, %0;" : "+l"(d) : "l"(a), "l"(b));
}
__device__ __forceinline__ ull fadd2(ull a, ull b) {
    ull r;
    asm("add.rn.f32x2 %0, %1, %2;" : "=l"(r) : "l"(a), "l"(b));
    return r;
}
__device__ __forceinline__ void f2un(float& lo, float& hi, ull v) {
    asm("mov.b64 {%0, %1}, %2;" : "=f"(lo), "=f"(hi) : "l"(v));
}

__global__ void k_tables() {
    int t = threadIdx.x;
    g_ct[t] = cospif(t / 128.0f);
    g_st[t] = sinpif(t / 128.0f);
}

// fw[l][i][o][kx][ky][2] -> g_W[l][kxi][ky][i][o][2]
__global__ __launch_bounds__(256) void k_wpack(const float* __restrict__ fw1,
                                               const float* __restrict__ fw2) {
    int idx = blockIdx.x * 256 + threadIdx.x;   // 524288 total
    int o = idx & 63, i = (idx >> 6) & 63, kxi = (idx >> 12) & 31, l = idx >> 17;
    const float* src = (kxi < 16)
        ? fw1 + (size_t)(((l * 64 + i) * 64 + o) * 16 + kxi) * 32
        : fw2 + (size_t)(((l * 64 + i) * 64 + o) * 16 + (kxi - 16)) * 32;
    float4 v[8];
#pragma unroll
    for (int q = 0; q < 8; q++) v[q] = ((const float4*)src)[q];
    const float* vf = (const float*)v;
    float2* dst = (float2*)g_W + ((size_t)(l * 32 + kxi) * 1024 + i) * 64 + o;
#pragma unroll
    for (int ky = 0; ky < 16; ky++)
        dst[(size_t)ky * 4096] = make_float2(vf[ky * 2], vf[ky * 2 + 1]);
}

// Fused inproj + fwd real DFT over n (layer 0):
// thread = (cg, nq, kyg) with cg = bits{0-2,5}, nq = bits{3,4}, kyg = bits{6,7}
// (cg in low bits of each quarter-warp -> conflict-free LDS.128)
__global__ __launch_bounds__(256) void k_fftn(const float* __restrict__ x,
                                              const float* __restrict__ in_w,
                                              const float* __restrict__ in_b) {
    __shared__ float hs[4096];          // 64n x 64c chunk
    __shared__ ull pcs[256];            // (cos, -sin)
    __shared__ float xs[768];           // 256n x 3
    __shared__ float w[320], bsh[64];
    int tid = threadIdx.x, bm = blockIdx.x;
    pcs[tid] = f2pk(cospif(tid / 128.0f), -sinpif(tid / 128.0f));
    w[tid] = in_w[tid & 255];
    if (tid < 64) { w[256 + tid] = in_w[256 + tid]; bsh[tid] = in_b[tid]; }
    const float* xp = x + (size_t)bm * 768;
    xs[tid] = xp[tid];
    xs[tid + 256] = xp[tid + 256];
    xs[tid + 512] = xp[tid + 512];
    int m = bm & 255;
    float pm = (2 * m + 1) * (1.0f / 256.0f) - 1.0f;
    int cg = (tid & 7) | ((tid >> 2) & 8);
    int nq = (tid >> 3) & 3;
    int kyg = tid >> 6;
    int c = cg * 4;
    ull acc[4][4];
#pragma unroll
    for (int kk = 0; kk < 4; kk++)
#pragma unroll
        for (int ci = 0; ci < 4; ci++) acc[kk][ci] = 0ull;
    for (int ch = 0; ch < 4; ch++) {
        __syncthreads();
#pragma unroll
        for (int it = 0; it < 16; it++) {
            int e = tid + 256 * it;
            int nloc = e >> 6, cc = e & 63;
            int n = ch * 64 + nloc;
            float pn = (2 * n + 1) * (1.0f / 256.0f) - 1.0f;
            float x0 = xs[n * 3], x1 = xs[n * 3 + 1], x2 = xs[n * 3 + 2];
            hs[e] = bsh[cc] + x0 * w[cc] + x1 * w[64 + cc] + x2 * w[128 + cc]
                  + pm * w[192 + cc] + pn * w[256 + cc];
        }
        __syncthreads();
#pragma unroll 4
        for (int j = 0; j < 16; j++) {
            int nloc = nq * 16 + j;
            int n = ch * 64 + nloc;
            float4 hv = *(const float4*)(hs + nloc * 64 + c);
            ull h0 = fdup(hv.x), h1 = fdup(hv.y), h2 = fdup(hv.z), h3 = fdup(hv.w);
#pragma unroll
            for (int kk = 0; kk < 4; kk++) {
                ull wv = pcs[((kyg * 4 + kk) * n) & 255];
                ffma2(acc[kk][0], h0, wv);
                ffma2(acc[kk][1], h1, wv);
                ffma2(acc[kk][2], h2, wv);
                ffma2(acc[kk][3], h3, wv);
            }
        }
    }
#pragma unroll
    for (int kk = 0; kk < 4; kk++)
#pragma unroll
        for (int ci = 0; ci < 4; ci++) {
            ull v = acc[kk][ci];
            v = fadd2(v, __shfl_xor_sync(0xffffffffu, v, 8));
            v = fadd2(v, __shfl_xor_sync(0xffffffffu, v, 16));
            acc[kk][ci] = v;
        }
    if (nq == 0) {
        ull* gp = (ull*)g_G + (size_t)bm * 1024 + cg * 4;
#pragma unroll
        for (int kk = 0; kk < 4; kk++) {
            int ky = kyg * 4 + kk;
#pragma unroll
            for (int ci = 0; ci < 4; ci++) gp[ky * 64 + ci] = acc[kk][ci];
        }
    }
}

// fwd complex DFT over m: X[kxi][c] = sum_m G[m][c] e^{-i 2pi kx m/256}
__global__ __launch_bounds__(512) void k_fftm() {
    __shared__ float2 Gc[4096];
    __shared__ float cts[256], sts[256];
    int tid = threadIdx.x;
    int b = blockIdx.x >> 4, ky = blockIdx.x & 15;
    if (tid < 256) { cts[tid] = g_ct[tid]; sts[tid] = g_st[tid]; }
    int kxi = tid >> 4, c = (tid & 15) * 4;
    int kx = kxi < 16 ? kxi : kxi + 224;
    float xr0 = 0, xr1 = 0, xr2 = 0, xr3 = 0, xi0 = 0, xi1 = 0, xi2 = 0, xi3 = 0;
    const float2* src = (const float2*)g_G;
    for (int m0 = 0; m0 < 256; m0 += 64) {
        __syncthreads();
#pragma unroll
        for (int it = 0; it < 8; it++) {
            int e = tid + 512 * it;
            Gc[e] = src[((b * 256 + m0 + (e >> 6)) * 16 + ky) * 64 + (e & 63)];
        }
        __syncthreads();
#pragma unroll 4
        for (int ml = 0; ml < 64; ml++) {
            int t = (kx * (m0 + ml)) & 255;
            float cv = cts[t], sv = sts[t];
            const float4* gg = (const float4*)(Gc + ml * 64 + c);
            float4 a = gg[0], d = gg[1];
            xr0 += a.x * cv + a.y * sv;  xi0 += a.y * cv - a.x * sv;
            xr1 += a.z * cv + a.w * sv;  xi1 += a.w * cv - a.z * sv;
            xr2 += d.x * cv + d.y * sv;  xi2 += d.y * cv - d.x * sv;
            xr3 += d.z * cv + d.w * sv;  xi3 += d.w * cv - d.z * sv;
        }
    }
    float4* dst = (float4*)(g_X + ((size_t)((b * 32 + kxi) * 16 + ky) * 64 + c) * 2);
    dst[0] = make_float4(xr0, xi0, xr1, xi1);
    dst[1] = make_float4(xr2, xi2, xr3, xi3);
}

// per-mode complex mix
__global__ __launch_bounds__(512) void k_mode(int l) {
    __shared__ float2 Xs[512];
    int tid = threadIdx.x;
    int kxi = blockIdx.x >> 4, ky = blockIdx.x & 15;
    Xs[tid] = ((const float2*)g_X)[(((tid >> 6) * 32 + kxi) * 16 + ky) * 64 + (tid & 63)];
    __syncthreads();
    int b = tid >> 6, o = tid & 63;
    const float2* wp = ((const float2*)g_W) + (size_t)((l * 32 + kxi) * 16 + ky) * 4096;
    float orr = 0.f, oii = 0.f;
#pragma unroll 8
    for (int i = 0; i < 64; i++) {
        float2 xv = Xs[b * 64 + i];
        float2 wv = wp[i * 64 + o];
        orr += xv.x * wv.x - xv.y * wv.y;
        oii += xv.x * wv.y + xv.y * wv.x;
    }
    ((float2*)g_O)[((b * 32 + kxi) * 16 + ky) * 64 + o] = make_float2(orr, oii);
}

// inverse complex DFT over m
__global__ __launch_bounds__(512) void k_ifftm() {
    __shared__ float2 Os[2048];
    __shared__ float cts[256], sts[256];
    int tid = threadIdx.x;
    int b = blockIdx.x >> 4, ky = blockIdx.x & 15;
    if (tid < 256) { cts[tid] = g_ct[tid]; sts[tid] = g_st[tid]; }
#pragma unroll
    for (int it = 0; it < 4; it++) {
        int e = tid + 512 * it;
        Os[e] = ((const float2*)g_O)[((b * 32 + (e >> 6)) * 16 + ky) * 64 + (e & 63)];
    }
    __syncthreads();
    int o = (tid & 15) * 4, mg = tid >> 4;
    for (int p = 0; p < 2; p++) {
        float yr[4][4], yi[4][4];
#pragma unroll
        for (int i = 0; i < 4; i++)
#pragma unroll
            for (int q = 0; q < 4; q++) { yr[i][q] = 0.f; yi[i][q] = 0.f; }
#pragma unroll 2
        for (int kxi = 0; kxi < 32; kxi++) {
            int kx = kxi < 16 ? kxi : kxi + 224;
            const float4* os4 = (const float4*)(Os + kxi * 64 + o);
            float4 a = os4[0], d = os4[1];
#pragma unroll
            for (int i = 0; i < 4; i++) {
                int m = mg + 32 * i + 128 * p;
                int t = (kx * m) & 255;
                float cv = cts[t], sv = sts[t];
                yr[i][0] += a.x * cv - a.y * sv;  yi[i][0] += a.x * sv + a.y * cv;
                yr[i][1] += a.z * cv - a.w * sv;  yi[i][1] += a.z * sv + a.w * cv;
                yr[i][2] += d.x * cv - d.y * sv;  yi[i][2] += d.x * sv + d.y * cv;
                yr[i][3] += d.z * cv - d.w * sv;  yi[i][3] += d.z * sv + d.w * cv;
            }
        }
#pragma unroll
        for (int i = 0; i < 4; i++) {
            int m = mg + 32 * i + 128 * p;
            float4* dst = (float4*)(g_Y + ((size_t)((b * 256 + m) * 16 + ky) * 64 + o) * 2);
            dst[0] = make_float4(yr[i][0], yi[i][0], yr[i][1], yi[i][1]);
            dst[1] = make_float4(yr[i][2], yi[i][2], yr[i][3], yi[i][3]);
        }
    }
}

// ---- shared phases for the fused iffn kernels ----
// Phase A: inverse real DFT over n -> ys (stride 68)
// Phase B: residual dense + relu   -> ys
__device__ __forceinline__ void iffn_AB(float* ys, float* Sre, float* Sim,
                                        float* lbs, float* lws,
                                        ull* pcc, ull* pss,
                                        const float* lw, const float* lb,
                                        int tid, int bm) {
#pragma unroll
    for (int it = 0; it < 16; it++) lws[tid + 256 * it] = lw[tid + 256 * it];
    if (tid < 64) lbs[tid] = lb[tid];
    float ct = cospif(tid / 128.0f), st = sinpif(tid / 128.0f);
    pcc[tid] = f2pk(ct, ct);
    pss[tid] = f2pk(st, st);
    const float2* Yp = (const float2*)g_Y + (size_t)bm * 1024;
#pragma unroll
    for (int it = 0; it < 4; it++) {
        int e = tid + 256 * it;
        int ky = e >> 6, o = e & 63;
        float2 v = Yp[e];
        float sc = (ky == 0 ? 1.f : 2.f) * (1.f / 65536.f);
        Sre[ky * 64 + o] = v.x * sc;
        Sim[ky * 64 + o] = -v.y * sc;   // negated: y += sr*cos + nsi*sin
    }
    __syncthreads();
    // Phase A
    {
        int o2 = (tid & 31) * 2, ng = tid >> 5;
        ull psr[16], pns[16];
#pragma unroll
        for (int ky = 0; ky < 16; ky++) {
            float2 re = *(const float2*)(Sre + ky * 64 + o2);
            float2 ni = *(const float2*)(Sim + ky * 64 + o2);
            psr[ky] = f2pk(re.x, re.y);
            pns[ky] = f2pk(ni.x, ni.y);
        }
        for (int j = 0; j < 32; j++) {
            int n = ng * 32 + j;
            ull acc = 0ull;
#pragma unroll
            for (int ky = 0; ky < 16; ky++) {
                int t = (ky * n) & 255;
                ffma2(acc, psr[ky], pcc[t]);
                ffma2(acc, pns[ky], pss[t]);
            }
            *(ull*)(ys + n * 68 + o2) = acc;
        }
    }
    __syncthreads();
    // Phase B: thread = point n
    {
        int n = tid;
        float yv[64];
#pragma unroll
        for (int c4 = 0; c4 < 64; c4 += 4) {
            float4 v = *(const float4*)(ys + n * 68 + c4);
            yv[c4] = v.x; yv[c4 + 1] = v.y; yv[c4 + 2] = v.z; yv[c4 + 3] = v.w;
        }
#pragma unroll
        for (int g = 0; g < 4; g++) {
            int o0 = g * 16;
            ull acc[8];
#pragma unroll
            for (int q = 0; q < 8; q++) acc[q] = f2pk(lbs[o0 + 2 * q], lbs[o0 + 2 * q + 1]);
#pragma unroll 8
            for (int c = 0; c < 64; c++) {
                ull hd = fdup(yv[c]);
                const ulonglong2* wp = (const ulonglong2*)(lws + c * 64 + o0);
#pragma unroll
                for (int q = 0; q < 4; q++) {
                    ulonglong2 w = wp[q];
                    ffma2(acc[2 * q], hd, w.x);
                    ffma2(acc[2 * q + 1], hd, w.y);
                }
            }
#pragma unroll
            for (int q = 0; q < 8; q++) {
                float a0, a1;
                f2un(a0, a1, acc[q]);
                float h0 = yv[o0 + 2 * q] + a0;
                float h1 = yv[o0 + 2 * q + 1] + a1;
                *(ull*)(ys + n * 68 + o0 + 2 * q) =
                    f2pk(h0 > 0.f ? h0 : 0.f, h1 > 0.f ? h1 : 0.f);
            }
        }
    }
    __syncthreads();
}

// fused iffn (layers 0-2): phases A,B then C = forward-n DFT of next layer -> g_G
__global__ __launch_bounds__(256) void k_iffn_fg(const float* __restrict__ lw,
                                                 const float* __restrict__ lb) {
    extern __shared__ float sm[];
    float* ys  = sm;                                 // 17408
    float* Sre = sm + 17408;                         // 1024
    float* Sim = sm + 18432;                         // 1024
    float* lbs = sm + 19456;                         // 64
    float* lws = sm + 19520;                         // 4096
    ull* pcc = (ull*)(sm + 23616);                   // 512 floats
    ull* pss = (ull*)(sm + 24128);                   // 512
    ull* pcs = (ull*)(sm + 24640);                   // 512 -> total 25152 floats
    int tid = threadIdx.x, bm = blockIdx.x;
    pcs[tid] = f2pk(cospif(tid / 128.0f), -sinpif(tid / 128.0f));
    iffn_AB(ys, Sre, Sim, lbs, lws, pcc, pss, lw, lb, tid, bm);
    // Phase C: G[ky][c] = sum_n h[n][c] e^{-i 2pi ky n/256}
    int cg = (tid & 7) | ((tid >> 2) & 8);
    int nq = (tid >> 3) & 3;
    int kyg = tid >> 6;
    int c = cg * 4;
    ull acc[4][4];
#pragma unroll
    for (int kk = 0; kk < 4; kk++)
#pragma unroll
        for (int ci = 0; ci < 4; ci++) acc[kk][ci] = 0ull;
#pragma unroll 4
    for (int j = 0; j < 64; j++) {
        int n = nq * 64 + j;
        float4 hv = *(const float4*)(ys + n * 68 + c);
        ull h0 = fdup(hv.x), h1 = fdup(hv.y), h2 = fdup(hv.z), h3 = fdup(hv.w);
#pragma unroll
        for (int kk = 0; kk < 4; kk++) {
            ull w = pcs[((kyg * 4 + kk) * n) & 255];
            ffma2(acc[kk][0], h0, w);
            ffma2(acc[kk][1], h1, w);
            ffma2(acc[kk][2], h2, w);
            ffma2(acc[kk][3], h3, w);
        }
    }
#pragma unroll
    for (int kk = 0; kk < 4; kk++)
#pragma unroll
        for (int ci = 0; ci < 4; ci++) {
            ull v = acc[kk][ci];
            v = fadd2(v, __shfl_xor_sync(0xffffffffu, v, 8));
            v = fadd2(v, __shfl_xor_sync(0xffffffffu, v, 16));
            acc[kk][ci] = v;
        }
    if (nq == 0) {
        ull* gp = (ull*)g_G + (size_t)bm * 1024 + cg * 4;
#pragma unroll
        for (int kk = 0; kk < 4; kk++) {
            int ky = kyg * 4 + kk;
#pragma unroll
            for (int ci = 0; ci < 4; ci++) gp[ky * 64 + ci] = acc[kk][ci];
        }
    }
}

// fused iffn (layer 3): phases A,B then D = output head -> out
__global__ __launch_bounds__(256) void k_iffn_head(const float* __restrict__ lw,
                                                   const float* __restrict__ lb,
                                                   const float* __restrict__ w1,
                                                   const float* __restrict__ b1,
                                                   const float* __restrict__ w2,
                                                   const float* __restrict__ b2,
                                                   float* __restrict__ out) {
    extern __shared__ float sm[];
    float* ys  = sm;                                 // 17408
    float* Sre = sm + 17408;
    float* Sim = sm + 18432;
    float* lbs = sm + 19456;
    float* U   = sm + 19520;                         // 8448 union
    float* lws = U;
    ull* pcc = (ull*)(U + 4096);
    ull* pss = (ull*)(U + 4608);
    int tid = threadIdx.x, bm = blockIdx.x;
    iffn_AB(ys, Sre, Sim, lbs, lws, pcc, pss, lw, lb, tid, bm);
    // Phase D: out = relu(h @ W1 + b1) @ W2 + b2  (overlay U with head weights)
    float* w1s = U;              // 8192
    float* w2s = U + 8192;       // 128
    float* b1s = U + 8320;       // 128
#pragma unroll
    for (int it = 0; it < 32; it++) w1s[tid + 256 * it] = w1[tid + 256 * it];
    if (tid < 128) { w2s[tid] = w2[tid]; b1s[tid] = b1[tid]; }
    __syncthreads();
    float hr[64];
#pragma unroll
    for (int c4 = 0; c4 < 64; c4 += 4) {
        float4 v = *(const float4*)(ys + tid * 68 + c4);
        hr[c4] = v.x; hr[c4 + 1] = v.y; hr[c4 + 2] = v.z; hr[c4 + 3] = v.w;
    }
    float accf = b2[0];
#pragma unroll
    for (int g = 0; g < 4; g++) {
        int j0 = g * 32;
        ull acc[16];
#pragma unroll
        for (int q = 0; q < 16; q++) acc[q] = f2pk(b1s[j0 + 2 * q], b1s[j0 + 2 * q + 1]);
#pragma unroll 4
        for (int c = 0; c < 64; c++) {
            ull hd = fdup(hr[c]);
            const ulonglong2* wp = (const ulonglong2*)(w1s + c * 128 + j0);
#pragma unroll
            for (int q = 0; q < 8; q++) {
                ulonglong2 w = wp[q];
                ffma2(acc[2 * q], hd, w.x);
                ffma2(acc[2 * q + 1], hd, w.y);
            }
        }
#pragma unroll
        for (int q = 0; q < 16; q++) {
            float a0, a1;
            f2un(a0, a1, acc[q]);
            accf += (a0 > 0.f ? a0 : 0.f) * w2s[j0 + 2 * q]
                  + (a1 > 0.f ? a1 : 0.f) * w2s[j0 + 2 * q + 1];
        }
    }
    out[(size_t)bm * 256 + tid] = accf;
}

extern "C" void kernel_launch(void* const* d_in, const int* in_sizes, int n_in,
                              void* d_out, int out_size) {
    const float* x     = (const float*)d_in[0];
    const float* in_w  = (const float*)d_in[1];
    const float* in_b  = (const float*)d_in[2];
    const float* fw1   = (const float*)d_in[3];
    const float* fw2   = (const float*)d_in[4];
    const float* lin_w = (const float*)d_in[5];
    const float* lin_b = (const float*)d_in[6];
    const float* o1w   = (const float*)d_in[7];
    const float* o1b   = (const float*)d_in[8];
    const float* o2w   = (const float*)d_in[9];
    const float* o2b   = (const float*)d_in[10];
    float* out = (float*)d_out;

    cudaFuncSetAttribute(k_iffn_fg,   cudaFuncAttributeMaxDynamicSharedMemorySize, 100608);
    cudaFuncSetAttribute(k_iffn_head, cudaFuncAttributeMaxDynamicSharedMemorySize, 111872);

    k_tables<<<1, 256>>>();
    k_wpack<<<2048, 256>>>(fw1, fw2);
    k_fftn<<<2048, 256>>>(x, in_w, in_b);
    for (int l = 0; l < 4; l++) {
        k_fftm<<<128, 512>>>();
        k_mode<<<512, 512>>>(l);
        k_ifftm<<<128, 512>>>();
        if (l < 3)
            k_iffn_fg<<<2048, 256, 100608>>>(lin_w + l * 4096, lin_b + l * 64);
        else
            k_iffn_head<<<2048, 256, 111872>>>(lin_w + l * 4096, lin_b + l * 64,
                                               o1w, o1b, o2w, o2b, out);
    }
}